// round 1
// baseline (speedup 1.0000x reference)
#include <cuda_runtime.h>
#include <cuda_bf16.h>
#include <math.h>

#define BSZ   32
#define LSEQ  1024
#define DIM   512
#define MTOT  (BSZ*LSEQ)          // 32768
#define GDIM  2048                // 4*DIM
#define GRID_BLOCKS 128

// ---------------- scratch (device globals; no allocation in kernel_launch) ---
__device__ float g_hA[MTOT*DIM];
__device__ float g_hB[MTOT*DIM];
__device__ float g_gpre[2][(size_t)MTOT*GDIM];   // [dir][(t*32+b)*2048 + n]
__device__ float g_hstate[2][2][BSZ*DIM];        // [parity][dir][b*512+d]
__device__ float g_alpha[3][DIM];
__device__ float g_beta[3][DIM];
__device__ unsigned g_bar_arrive;
__device__ unsigned g_bar_gen;

// ---------------- small helpers ---------------------------------------------
__device__ __forceinline__ float sigmoidf_(float x) {
    return 1.0f / (1.0f + __expf(-x));
}

__device__ __forceinline__ void grid_sync_() {
    __threadfence();
    __syncthreads();
    if (threadIdx.x == 0) {
        unsigned cur = *(volatile unsigned*)&g_bar_gen;
        unsigned a = atomicAdd(&g_bar_arrive, 1u);
        if (a == GRID_BLOCKS - 1) {
            g_bar_arrive = 0u;
            __threadfence();
            atomicAdd(&g_bar_gen, 1u);
        } else {
            while (*(volatile unsigned*)&g_bar_gen == cur) { }
        }
    }
    __syncthreads();
}

// ---------------- BN fold: alpha = s*rsqrt(v+eps); beta = (bias-m)*alpha + o --
__global__ void bnprep_kernel(
    const float* __restrict__ b1, const float* __restrict__ s1, const float* __restrict__ o1,
    const float* __restrict__ m1, const float* __restrict__ v1,
    const float* __restrict__ b2, const float* __restrict__ s2, const float* __restrict__ o2,
    const float* __restrict__ m2, const float* __restrict__ v2,
    const float* __restrict__ b3, const float* __restrict__ s3, const float* __restrict__ o3,
    const float* __restrict__ m3, const float* __restrict__ v3)
{
    int i = threadIdx.x;
    if (i < DIM) {
        float g;
        g = s1[i] * rsqrtf(v1[i] + 1e-5f); g_alpha[0][i] = g; g_beta[0][i] = (b1[i] - m1[i]) * g + o1[i];
        g = s2[i] * rsqrtf(v2[i] + 1e-5f); g_alpha[1][i] = g; g_beta[1][i] = (b2[i] - m2[i]) * g + o2[i];
        g = s3[i] * rsqrtf(v3[i] + 1e-5f); g_alpha[2][i] = g; g_beta[2][i] = (b3[i] - m3[i]) * g + o3[i];
    }
}

// ---------------- embedding gather ------------------------------------------
__global__ void embed_kernel(const int* __restrict__ x, const float* __restrict__ ew)
{
    int m = blockIdx.x;
    int tok = x[m];
    const float4* src = (const float4*)(ew + (size_t)tok * DIM);
    float4* dst = (float4*)(g_hA + (size_t)m * DIM);
    dst[threadIdx.x] = src[threadIdx.x];   // 128 threads * float4 = 512 floats
}

// ---------------- conv(k=3, SAME) + BN + ReLU as shifted GEMM ----------------
// C[m][n] = relu( alpha[n] * sum_{w,k} A[m + w - 1][k] * Wc[(w*512+k)*512 + n] + beta[n] )
__global__ void __launch_bounds__(256) conv_gemm_kernel(
    const float* __restrict__ Wc, int sel, int layer)
{
    __shared__ __align__(16) float As[16][132];
    __shared__ __align__(16) float Bs[16][64];

    const float* A   = sel ? g_hB : g_hA;
    float*       dst = sel ? g_hA : g_hB;

    const int tid = threadIdx.x;
    const int m0 = blockIdx.x * 128;
    const int n0 = blockIdx.y * 64;
    const int t0 = m0 & (LSEQ - 1);   // rows of a tile share one batch element

    const int tm = (tid >> 4) << 3;   // 0..120 step 8
    const int tn = (tid & 15) << 2;   // 0..60  step 4

    float acc[8][4];
    #pragma unroll
    for (int i = 0; i < 8; i++)
        #pragma unroll
        for (int j = 0; j < 4; j++) acc[i][j] = 0.f;

    for (int kk = 0; kk < 1536; kk += 16) {
        const int w = kk >> 9;          // tap 0..2
        const int kbase = kk & 511;
        // ---- load A tile (128 x 16), with shift/zero boundary ----
        #pragma unroll
        for (int i = 0; i < 2; i++) {
            int idx = i * 256 + tid;         // 0..511 float4 slots
            int row = idx >> 2;
            int kq  = (idx & 3) << 2;
            int tp  = t0 + row + w - 1;
            float4 v = make_float4(0.f, 0.f, 0.f, 0.f);
            if (tp >= 0 && tp < LSEQ) {
                v = *(const float4*)(A + (size_t)(m0 + row + w - 1) * DIM + kbase + kq);
            }
            As[kq + 0][row] = v.x;
            As[kq + 1][row] = v.y;
            As[kq + 2][row] = v.z;
            As[kq + 3][row] = v.w;
        }
        // ---- load B tile (16 x 64), Wc is contiguous [1536][512] ----
        {
            int krow = tid >> 4;
            int nq   = (tid & 15) << 2;
            float4 v = *(const float4*)(Wc + (size_t)(kk + krow) * DIM + n0 + nq);
            *(float4*)&Bs[krow][nq] = v;
        }
        __syncthreads();
        #pragma unroll
        for (int k = 0; k < 16; k++) {
            float4 a0 = *(const float4*)&As[k][tm];
            float4 a1 = *(const float4*)&As[k][tm + 4];
            float4 bv = *(const float4*)&Bs[k][tn];
            float av[8] = {a0.x, a0.y, a0.z, a0.w, a1.x, a1.y, a1.z, a1.w};
            float bw[4] = {bv.x, bv.y, bv.z, bv.w};
            #pragma unroll
            for (int i = 0; i < 8; i++)
                #pragma unroll
                for (int j = 0; j < 4; j++)
                    acc[i][j] = fmaf(av[i], bw[j], acc[i][j]);
        }
        __syncthreads();
    }

    float al[4], be[4];
    #pragma unroll
    for (int j = 0; j < 4; j++) {
        al[j] = g_alpha[layer][n0 + tn + j];
        be[j] = g_beta [layer][n0 + tn + j];
    }
    #pragma unroll
    for (int i = 0; i < 8; i++) {
        float4 o;
        o.x = fmaxf(fmaf(acc[i][0], al[0], be[0]), 0.f);
        o.y = fmaxf(fmaf(acc[i][1], al[1], be[1]), 0.f);
        o.z = fmaxf(fmaf(acc[i][2], al[2], be[2]), 0.f);
        o.w = fmaxf(fmaf(acc[i][3], al[3], be[3]), 0.f);
        *(float4*)(dst + (size_t)(m0 + tm + i) * DIM + n0 + tn) = o;
    }
}

// ---------------- gates precompute: gpre[dir][t][b][n] = h @ Wx + bias --------
__global__ void __launch_bounds__(256) gates_gemm_kernel(
    const float* __restrict__ W, const float* __restrict__ bias, int dir)
{
    __shared__ __align__(16) float As[16][132];
    __shared__ __align__(16) float Bs[16][64];

    const float* A = g_hB;  // conv3 output
    float* dst = g_gpre[dir];

    const int tid = threadIdx.x;
    const int m0 = blockIdx.x * 128;
    const int n0 = blockIdx.y * 64;

    const int tm = (tid >> 4) << 3;
    const int tn = (tid & 15) << 2;

    float acc[8][4];
    #pragma unroll
    for (int i = 0; i < 8; i++)
        #pragma unroll
        for (int j = 0; j < 4; j++) acc[i][j] = 0.f;

    for (int kk = 0; kk < 512; kk += 16) {
        #pragma unroll
        for (int i = 0; i < 2; i++) {
            int idx = i * 256 + tid;
            int row = idx >> 2;
            int kq  = (idx & 3) << 2;
            float4 v = *(const float4*)(A + (size_t)(m0 + row) * DIM + kk + kq);
            As[kq + 0][row] = v.x;
            As[kq + 1][row] = v.y;
            As[kq + 2][row] = v.z;
            As[kq + 3][row] = v.w;
        }
        {
            int krow = tid >> 4;
            int nq   = (tid & 15) << 2;
            float4 v = *(const float4*)(W + (size_t)(kk + krow) * GDIM + n0 + nq);
            *(float4*)&Bs[krow][nq] = v;
        }
        __syncthreads();
        #pragma unroll
        for (int k = 0; k < 16; k++) {
            float4 a0 = *(const float4*)&As[k][tm];
            float4 a1 = *(const float4*)&As[k][tm + 4];
            float4 bv = *(const float4*)&Bs[k][tn];
            float av[8] = {a0.x, a0.y, a0.z, a0.w, a1.x, a1.y, a1.z, a1.w};
            float bw[4] = {bv.x, bv.y, bv.z, bv.w};
            #pragma unroll
            for (int i = 0; i < 8; i++)
                #pragma unroll
                for (int j = 0; j < 4; j++)
                    acc[i][j] = fmaf(av[i], bw[j], acc[i][j]);
        }
        __syncthreads();
    }

    float bb[4];
    #pragma unroll
    for (int j = 0; j < 4; j++) bb[j] = bias[n0 + tn + j];
    #pragma unroll
    for (int i = 0; i < 8; i++) {
        int m = m0 + tm + i;
        int b = m >> 10;
        int t = m & (LSEQ - 1);
        float4 o;
        o.x = acc[i][0] + bb[0];
        o.y = acc[i][1] + bb[1];
        o.z = acc[i][2] + bb[2];
        o.w = acc[i][3] + bb[3];
        *(float4*)(dst + (size_t)((t << 5) + b) * GDIM + n0 + tn) = o;
    }
}

// ---------------- persistent bidirectional LSTM recurrence -------------------
// 128 blocks: blocks [0,64) forward, [64,128) backward. Block owns 8 hidden dims.
__global__ void __launch_bounds__(256, 1) lstm_recur_kernel(
    const float* __restrict__ wf, const float* __restrict__ wb,
    const int* __restrict__ lengths, float* __restrict__ out)
{
    extern __shared__ float sm[];
    float* Wt = sm;               // [32][516]: W_h^T slice, padded row stride 516
    float* hs = sm + 32 * 516;    // [32][516]: staged h_prev, padded

    __shared__ int len_s[32];

    const int tid = threadIdx.x;
    const int dir = blockIdx.x >> 6;
    const int dc  = (blockIdx.x & 63) << 3;          // base hidden dim of this block
    const float* w = dir ? wb : wf;

    // load W_h^T slice: Wt[nl][k] = w[(512+k)*2048 + col(nl)]
    for (int idx = tid; idx < 32 * 512; idx += 256) {
        int nl = idx & 31;
        int k  = idx >> 5;
        int c  = ((nl >> 3) << 9) + dc + (nl & 7);   // gate*512 + dc + j
        Wt[nl * 516 + k] = w[(size_t)(512 + k) * GDIM + c];
    }
    if (tid < 32) len_s[tid] = lengths[tid];
    {   // zero parity-0 h for this block's columns
        int b = tid >> 3, j = tid & 7;
        g_hstate[0][dir][b * DIM + dc + j] = 0.f;
    }
    grid_sync_();

    const int tx = tid & 31;      // gate-column within block: gate = tx/8, j = tx%8
    const int ty = tid >> 5;      // warp id -> batch group {ty, ty+8, ty+16, ty+24}
    const int jd = tx & 7;
    const int col = ((tx >> 3) << 9) + dc + jd;
    const float* gpre = g_gpre[dir];
    const float* wrow = Wt + tx * 516;
    const unsigned FULL = 0xffffffffu;

    float c0 = 0.f, c1 = 0.f, c2 = 0.f, c3 = 0.f;    // cell state (lanes tx<8 only)

    for (int s = 0; s < LSEQ; s++) {
        const int t = dir ? (LSEQ - 1 - s) : s;
        const int p = s & 1;
        const float4* hp4 = (const float4*)g_hstate[p][dir];
        float* hn = g_hstate[p ^ 1][dir];

        // stage h_prev to smem (L1-bypassing loads; apply backward reset here)
        #pragma unroll
        for (int i = 0; i < 16; i++) {
            int idx4 = i * 256 + tid;                 // 0..4095 float4
            int b = idx4 >> 7, kc = idx4 & 127;
            float4 v = __ldcg(hp4 + idx4);
            if (dir && t >= len_s[b] - 1) v = make_float4(0.f, 0.f, 0.f, 0.f);
            *(float4*)(hs + b * 516 + (kc << 2)) = v;
        }
        __syncthreads();

        // pre[b][col] = h_prev @ Wh  (4 batches per thread)
        const float* h0p = hs + (size_t)(ty     ) * 516;
        const float* h1p = hs + (size_t)(ty +  8) * 516;
        const float* h2p = hs + (size_t)(ty + 16) * 516;
        const float* h3p = hs + (size_t)(ty + 24) * 516;
        float a0 = 0.f, a1 = 0.f, a2 = 0.f, a3 = 0.f;
        #pragma unroll 4
        for (int kc = 0; kc < 128; kc++) {
            float4 wv = *(const float4*)(wrow + (kc << 2));
            float4 x0 = *(const float4*)(h0p + (kc << 2));
            float4 x1 = *(const float4*)(h1p + (kc << 2));
            float4 x2 = *(const float4*)(h2p + (kc << 2));
            float4 x3 = *(const float4*)(h3p + (kc << 2));
            a0 = fmaf(wv.x, x0.x, fmaf(wv.y, x0.y, fmaf(wv.z, x0.z, fmaf(wv.w, x0.w, a0))));
            a1 = fmaf(wv.x, x1.x, fmaf(wv.y, x1.y, fmaf(wv.z, x1.z, fmaf(wv.w, x1.w, a1))));
            a2 = fmaf(wv.x, x2.x, fmaf(wv.y, x2.y, fmaf(wv.z, x2.z, fmaf(wv.w, x2.w, a2))));
            a3 = fmaf(wv.x, x3.x, fmaf(wv.y, x3.y, fmaf(wv.z, x3.z, fmaf(wv.w, x3.w, a3))));
        }

        const float* gp = gpre + (size_t)(t << 5) * GDIM + col;
        float p0 = a0 + __ldg(gp + (size_t)(ty     ) * GDIM);
        float p1 = a1 + __ldg(gp + (size_t)(ty +  8) * GDIM);
        float p2 = a2 + __ldg(gp + (size_t)(ty + 16) * GDIM);
        float p3 = a3 + __ldg(gp + (size_t)(ty + 24) * GDIM);

        // gather i,g,f,o for dim jd from lanes jd, jd+8, jd+16, jd+24
        float vi0 = __shfl_sync(FULL, p0, jd),      vi1 = __shfl_sync(FULL, p1, jd);
        float vi2 = __shfl_sync(FULL, p2, jd),      vi3 = __shfl_sync(FULL, p3, jd);
        float vg0 = __shfl_sync(FULL, p0, jd + 8),  vg1 = __shfl_sync(FULL, p1, jd + 8);
        float vg2 = __shfl_sync(FULL, p2, jd + 8),  vg3 = __shfl_sync(FULL, p3, jd + 8);
        float vf0 = __shfl_sync(FULL, p0, jd + 16), vf1 = __shfl_sync(FULL, p1, jd + 16);
        float vf2 = __shfl_sync(FULL, p2, jd + 16), vf3 = __shfl_sync(FULL, p3, jd + 16);
        float vo0 = __shfl_sync(FULL, p0, jd + 24), vo1 = __shfl_sync(FULL, p1, jd + 24);
        float vo2 = __shfl_sync(FULL, p2, jd + 24), vo3 = __shfl_sync(FULL, p3, jd + 24);

        if (tx < 8) {
            const int d = dc + tx;
            // b = ty
            {
                int b = ty;
                float cc = (dir && t >= len_s[b] - 1) ? 0.f : c0;
                cc = sigmoidf_(vf0 + 1.f) * cc + sigmoidf_(vi0) * tanhf(vg0);
                c0 = cc;
                float hh = sigmoidf_(vo0) * tanhf(cc);
                hn[b * DIM + d] = hh;
                out[(((size_t)b << 10) + t) * 1024 + (dir << 9) + d] = hh;
            }
            {
                int b = ty + 8;
                float cc = (dir && t >= len_s[b] - 1) ? 0.f : c1;
                cc = sigmoidf_(vf1 + 1.f) * cc + sigmoidf_(vi1) * tanhf(vg1);
                c1 = cc;
                float hh = sigmoidf_(vo1) * tanhf(cc);
                hn[b * DIM + d] = hh;
                out[(((size_t)b << 10) + t) * 1024 + (dir << 9) + d] = hh;
            }
            {
                int b = ty + 16;
                float cc = (dir && t >= len_s[b] - 1) ? 0.f : c2;
                cc = sigmoidf_(vf2 + 1.f) * cc + sigmoidf_(vi2) * tanhf(vg2);
                c2 = cc;
                float hh = sigmoidf_(vo2) * tanhf(cc);
                hn[b * DIM + d] = hh;
                out[(((size_t)b << 10) + t) * 1024 + (dir << 9) + d] = hh;
            }
            {
                int b = ty + 24;
                float cc = (dir && t >= len_s[b] - 1) ? 0.f : c3;
                cc = sigmoidf_(vf3 + 1.f) * cc + sigmoidf_(vi3) * tanhf(vg3);
                c3 = cc;
                float hh = sigmoidf_(vo3) * tanhf(cc);
                hn[b * DIM + d] = hh;
                out[(((size_t)b << 10) + t) * 1024 + (dir << 9) + d] = hh;
            }
        }
        grid_sync_();
    }
}

// ---------------- launch ------------------------------------------------------
extern "C" void kernel_launch(void* const* d_in, const int* in_sizes, int n_in,
                              void* d_out, int out_size)
{
    (void)in_sizes; (void)n_in; (void)out_size;
    const int*   x        = (const int*)  d_in[0];
    const int*   lengths  = (const int*)  d_in[1];
    const float* embed_w  = (const float*)d_in[2];
    const float* c1w = (const float*)d_in[3];
    const float* c1b = (const float*)d_in[4];
    const float* c2w = (const float*)d_in[5];
    const float* c2b = (const float*)d_in[6];
    const float* c3w = (const float*)d_in[7];
    const float* c3b = (const float*)d_in[8];
    const float* wf  = (const float*)d_in[9];
    const float* bf  = (const float*)d_in[10];
    const float* wb  = (const float*)d_in[11];
    const float* bb  = (const float*)d_in[12];
    const float* s1 = (const float*)d_in[13]; const float* o1 = (const float*)d_in[14];
    const float* m1 = (const float*)d_in[15]; const float* v1 = (const float*)d_in[16];
    const float* s2 = (const float*)d_in[17]; const float* o2 = (const float*)d_in[18];
    const float* m2 = (const float*)d_in[19]; const float* v2 = (const float*)d_in[20];
    const float* s3 = (const float*)d_in[21]; const float* o3 = (const float*)d_in[22];
    const float* m3 = (const float*)d_in[23]; const float* v3 = (const float*)d_in[24];
    float* out = (float*)d_out;

    const int SMEM_RECUR = 2 * 32 * 516 * sizeof(float);   // 132096 B
    cudaFuncSetAttribute(lstm_recur_kernel,
                         cudaFuncAttributeMaxDynamicSharedMemorySize, SMEM_RECUR);

    bnprep_kernel<<<1, 512>>>(c1b, s1, o1, m1, v1,
                              c2b, s2, o2, m2, v2,
                              c3b, s3, o3, m3, v3);
    embed_kernel<<<MTOT, 128>>>(x, embed_w);

    dim3 gconv(MTOT / 128, DIM / 64);
    conv_gemm_kernel<<<gconv, 256>>>(c1w, 0, 0);  // hA -> hB
    conv_gemm_kernel<<<gconv, 256>>>(c2w, 1, 1);  // hB -> hA
    conv_gemm_kernel<<<gconv, 256>>>(c3w, 0, 2);  // hA -> hB

    dim3 ggate(MTOT / 128, GDIM / 64);
    gates_gemm_kernel<<<ggate, 256>>>(wf, bf, 0);
    gates_gemm_kernel<<<ggate, 256>>>(wb, bb, 1);

    lstm_recur_kernel<<<GRID_BLOCKS, 256, SMEM_RECUR>>>(wf, wb, lengths, out);
}

// round 3
// speedup vs baseline: 1.2302x; 1.2302x over previous
#include <cuda_runtime.h>
#include <cuda_bf16.h>
#include <stdint.h>
#include <math.h>

#define BSZ   32
#define LSEQ  1024
#define DIM   512
#define MTOT  (BSZ*LSEQ)          // 32768
#define GDIM  2048                // 4*DIM
#define GRID_BLOCKS 128

// =================== scratch (device globals) ================================
__device__ __align__(128) __nv_bfloat16 g_aHi[(size_t)MTOT*DIM];
__device__ __align__(128) __nv_bfloat16 g_aLo[(size_t)MTOT*DIM];
__device__ __align__(128) __nv_bfloat16 g_bHi[(size_t)MTOT*DIM];
__device__ __align__(128) __nv_bfloat16 g_bLo[(size_t)MTOT*DIM];
__device__ __align__(128) __nv_bfloat16 g_wConv[3][(size_t)DIM*4608];   // [layer][n][kk]
__device__ __align__(128) __nv_bfloat16 g_wGate[2][(size_t)GDIM*1536];  // [dir][n][kk]
__device__ float g_gpre[2][(size_t)MTOT*GDIM];   // [dir][(t*32+b)*2048 + n]
__device__ float g_hstate[2][2][BSZ*DIM];        // [parity][dir][b*512+d]
__device__ float g_alpha[3][DIM];
__device__ float g_beta[3][DIM];
__device__ unsigned g_bar_arrive;
__device__ unsigned g_bar_gen;

// =================== SW128 swizzle (128B rows) ================================
#define SWZ(off) ((off) ^ (((off) >> 3) & 0x70))

// =================== warp MMA primitives (family-portable, sm_80+) ===========
__device__ __forceinline__ uint32_t smem_to_u32(const void* p) {
    uint32_t a;
    asm("{ .reg .u64 t; cvta.to.shared.u64 t, %1; cvt.u32.u64 %0, t; }" : "=r"(a) : "l"(p));
    return a;
}
#define LDSM_X4(r0, r1, r2, r3, addr) \
    asm volatile("ldmatrix.sync.aligned.m8n8.x4.shared.b16 {%0,%1,%2,%3}, [%4];" \
        : "=r"(r0), "=r"(r1), "=r"(r2), "=r"(r3) : "r"(addr))
#define MMA16816(c, a, b) \
    asm volatile("mma.sync.aligned.m16n8k16.row.col.f32.bf16.bf16.f32 " \
        "{%0,%1,%2,%3}, {%4,%5,%6,%7}, {%8,%9}, {%0,%1,%2,%3};" \
        : "+f"((c)[0]), "+f"((c)[1]), "+f"((c)[2]), "+f"((c)[3]) \
        : "r"((a)[0]), "r"((a)[1]), "r"((a)[2]), "r"((a)[3]), \
          "r"((b)[0]), "r"((b)[1]))

// =================== misc helpers ============================================
__device__ __forceinline__ float sigmoidf_(float x) { return 1.0f / (1.0f + __expf(-x)); }

__device__ __forceinline__ void grid_sync_() {
    __threadfence();
    __syncthreads();
    if (threadIdx.x == 0) {
        unsigned cur = *(volatile unsigned*)&g_bar_gen;
        unsigned a = atomicAdd(&g_bar_arrive, 1u);
        if (a == GRID_BLOCKS - 1) {
            g_bar_arrive = 0u;
            __threadfence();
            atomicAdd(&g_bar_gen, 1u);
        } else {
            while (*(volatile unsigned*)&g_bar_gen == cur) { }
        }
    }
    __syncthreads();
}

// =================== BN fold =================================================
__global__ void bnprep_kernel(
    const float* __restrict__ b1, const float* __restrict__ s1, const float* __restrict__ o1,
    const float* __restrict__ m1, const float* __restrict__ v1,
    const float* __restrict__ b2, const float* __restrict__ s2, const float* __restrict__ o2,
    const float* __restrict__ m2, const float* __restrict__ v2,
    const float* __restrict__ b3, const float* __restrict__ s3, const float* __restrict__ o3,
    const float* __restrict__ m3, const float* __restrict__ v3)
{
    int i = threadIdx.x;
    if (i < DIM) {
        float g;
        g = s1[i] * rsqrtf(v1[i] + 1e-5f); g_alpha[0][i] = g; g_beta[0][i] = (b1[i] - m1[i]) * g + o1[i];
        g = s2[i] * rsqrtf(v2[i] + 1e-5f); g_alpha[1][i] = g; g_beta[1][i] = (b2[i] - m2[i]) * g + o2[i];
        g = s3[i] * rsqrtf(v3[i] + 1e-5f); g_alpha[2][i] = g; g_beta[2][i] = (b3[i] - m3[i]) * g + o3[i];
    }
}

// =================== weight prep: bf16 hi/lo sections ========================
__global__ void wprep_conv_kernel(const float* __restrict__ Wc, int layer)
{
    int idx = blockIdx.x * 256 + threadIdx.x;
    if (idx >= DIM * 4608) return;
    int n = idx / 4608, kk = idx % 4608;
    int s = kk / 1536, r = kk % 1536;
    float v = Wc[(size_t)r * DIM + n];
    __nv_bfloat16 h = __float2bfloat16(v);
    __nv_bfloat16 o = (s < 2) ? h : __float2bfloat16(v - __bfloat162float(h));
    g_wConv[layer][(size_t)n * 4608 + kk] = o;
}
__global__ void wprep_gate_kernel(const float* __restrict__ W, int dir)
{
    int idx = blockIdx.x * 256 + threadIdx.x;
    if (idx >= GDIM * 1536) return;
    int n = idx / 1536, kk = idx % 1536;
    int s = kk / 512, k = kk % 512;
    float v = W[(size_t)k * GDIM + n];
    __nv_bfloat16 h = __float2bfloat16(v);
    __nv_bfloat16 o = (s < 2) ? h : __float2bfloat16(v - __bfloat162float(h));
    g_wGate[dir][(size_t)n * 1536 + kk] = o;
}

// =================== embedding -> bf16 hi/lo =================================
__global__ void embed_kernel(const int* __restrict__ x, const float* __restrict__ ew)
{
    int m = blockIdx.x;
    int tok = x[m];
    int j = threadIdx.x;                       // 0..127
    float4 v = ((const float4*)(ew + (size_t)tok * DIM))[j];
    float f[4] = {v.x, v.y, v.z, v.w};
    __nv_bfloat16 h[4], l[4];
    #pragma unroll
    for (int i = 0; i < 4; i++) {
        h[i] = __float2bfloat16(f[i]);
        l[i] = __float2bfloat16(f[i] - __bfloat162float(h[i]));
    }
    *(uint2*)(g_aHi + (size_t)m * DIM + j * 4) = *(uint2*)h;
    *(uint2*)(g_aLo + (size_t)m * DIM + j * 4) = *(uint2*)l;
}

// =================== bf16 mma.sync GEMM (conv & gates) =======================
// D[128,128] = sum over K_eff of A_sec x B^T; A [m][k], B [n][k] K-major bf16.
// Tile 128x128, K-chunk 64. 8 warps: warp (wm = wid&3, wn = wid>>2) owns 32x64.
// conv: K_eff=4608 (3 terms x 3 taps x 512), row shift = tap-1, epi BN+ReLU+split
// gates: K_eff=1536 (3 terms x 512), epi +bias -> fp32 time-major
__global__ void __launch_bounds__(256) mma_gemm_kernel(
    const __nv_bfloat16* __restrict__ Ahi, const __nv_bfloat16* __restrict__ Alo,
    const __nv_bfloat16* __restrict__ Bw,  int Ktot, int convmode, int layer,
    __nv_bfloat16* __restrict__ outHi, __nv_bfloat16* __restrict__ outLo,
    const float* __restrict__ bias, float* __restrict__ gout)
{
    extern __shared__ char smem[];
    // stage layout: [bsel*32768 + {A:0, B:16384}], each tile 128 rows x 128B (SW128)
    const int tid = threadIdx.x;
    const int lane = tid & 31, wid = tid >> 5;
    const int wm = wid & 3, wn = wid >> 2;
    const int m0 = blockIdx.x * 128, n0 = blockIdx.y * 128;
    const int t0 = m0 & (LSEQ - 1);
    const uint32_t sb = smem_to_u32(smem);

    // per-lane ldmatrix address components (swizzle XOR = (lane&7)<<4 since
    // all tile base rows are multiples of 8)
    const uint32_t sx   = (uint32_t)(lane & 7) << 4;
    const uint32_t rowA = (uint32_t)(lane & 15) * 128u;
    const uint32_t hiA  = (uint32_t)(lane >> 4) * 16u;
    const uint32_t rowB = (uint32_t)(((lane >> 4) << 3) | (lane & 7)) * 128u;
    const uint32_t hiB  = (uint32_t)((lane >> 3) & 1) * 16u;

    float acc[2][8][4];
    #pragma unroll
    for (int a = 0; a < 2; a++)
        #pragma unroll
        for (int b = 0; b < 8; b++)
            #pragma unroll
            for (int c = 0; c < 4; c++) acc[a][b][c] = 0.f;

    const int nch = Ktot >> 6;       // 72 (conv) or 24 (gates)
    const int nsc = nch / 3;         // chunks per hi/lo term section

    #define DO_COPY(CC, BSEL) do { \
        int _cc = (CC); \
        int _s = _cc / nsc, _r = _cc - _s * nsc; \
        const __nv_bfloat16* _Asrc = (_s == 1) ? Alo : Ahi; \
        int _shift, _kb; \
        if (convmode) { _shift = (_r >> 3) - 1; _kb = (_r & 7) << 6; } \
        else          { _shift = 0;             _kb = _r << 6; } \
        const int _kk0 = _cc << 6; \
        char* _aP = smem + (BSEL) * 32768; \
        char* _bP = _aP + 16384; \
        _Pragma("unroll") \
        for (int _i = 0; _i < 4; _i++) { \
            int _idx = _i * 256 + tid; \
            int _rowl = _idx >> 3, _cq = (_idx & 7) << 3; \
            uint32_t _off = SWZ((uint32_t)(_rowl * 128 + _cq * 2)); \
            int _tl = t0 + _rowl + _shift; \
            uint4 _va = make_uint4(0u, 0u, 0u, 0u); \
            if (_tl >= 0 && _tl < LSEQ) \
                _va = *(const uint4*)(_Asrc + (size_t)(m0 + _rowl + _shift) * DIM + _kb + _cq); \
            *(uint4*)(_aP + _off) = _va; \
            uint4 _vb = *(const uint4*)(Bw + (size_t)(n0 + _rowl) * Ktot + _kk0 + _cq); \
            *(uint4*)(_bP + _off) = _vb; \
        } \
    } while (0)

    DO_COPY(0, 0);
    __syncthreads();

    for (int cc = 0; cc < nch; cc++) {
        const int bsel = cc & 1;
        if (cc + 1 < nch) DO_COPY(cc + 1, bsel ^ 1);

        const uint32_t aBase = sb + bsel * 32768 + (uint32_t)(wm * 32) * 128;
        const uint32_t bBase = sb + bsel * 32768 + 16384 + (uint32_t)(wn * 64) * 128;

        #pragma unroll
        for (int k16 = 0; k16 < 4; k16++) {
            const uint32_t kcA = ((uint32_t)(k16 * 32) + hiA) ^ sx;
            const uint32_t kcB = ((uint32_t)(k16 * 32) + hiB) ^ sx;
            uint32_t afr[2][4];
            #pragma unroll
            for (int mt = 0; mt < 2; mt++) {
                uint32_t ad = aBase + (uint32_t)(mt * 2048) + rowA + kcA;
                LDSM_X4(afr[mt][0], afr[mt][1], afr[mt][2], afr[mt][3], ad);
            }
            uint32_t bfr[8][2];
            #pragma unroll
            for (int np = 0; np < 4; np++) {
                uint32_t bd = bBase + (uint32_t)(np * 2048) + rowB + kcB;
                LDSM_X4(bfr[2*np][0], bfr[2*np][1], bfr[2*np+1][0], bfr[2*np+1][1], bd);
            }
            #pragma unroll
            for (int mt = 0; mt < 2; mt++)
                #pragma unroll
                for (int nt = 0; nt < 8; nt++)
                    MMA16816(acc[mt][nt], afr[mt], bfr[nt]);
        }
        __syncthreads();
    }
    #undef DO_COPY

    // ---- epilogue ----
    const int g  = lane >> 2;
    const int tg = lane & 3;
    if (gout == nullptr) {            // conv: BN + ReLU + bf16 hi/lo split
        #pragma unroll
        for (int mt = 0; mt < 2; mt++) {
            const int mlo = m0 + wm * 32 + mt * 16 + g;
            const int mhi = mlo + 8;
            #pragma unroll
            for (int nt = 0; nt < 8; nt++) {
                const int n = n0 + wn * 64 + nt * 8 + tg * 2;
                const float al0 = g_alpha[layer][n],     be0 = g_beta[layer][n];
                const float al1 = g_alpha[layer][n + 1], be1 = g_beta[layer][n + 1];
                float v00 = fmaxf(fmaf(acc[mt][nt][0], al0, be0), 0.f);
                float v01 = fmaxf(fmaf(acc[mt][nt][1], al1, be1), 0.f);
                float v10 = fmaxf(fmaf(acc[mt][nt][2], al0, be0), 0.f);
                float v11 = fmaxf(fmaf(acc[mt][nt][3], al1, be1), 0.f);
                __nv_bfloat16 h00 = __float2bfloat16(v00), h01 = __float2bfloat16(v01);
                __nv_bfloat16 h10 = __float2bfloat16(v10), h11 = __float2bfloat16(v11);
                __nv_bfloat16 l00 = __float2bfloat16(v00 - __bfloat162float(h00));
                __nv_bfloat16 l01 = __float2bfloat16(v01 - __bfloat162float(h01));
                __nv_bfloat16 l10 = __float2bfloat16(v10 - __bfloat162float(h10));
                __nv_bfloat16 l11 = __float2bfloat16(v11 - __bfloat162float(h11));
                __nv_bfloat162 ph0; ph0.x = h00; ph0.y = h01;
                __nv_bfloat162 ph1; ph1.x = h10; ph1.y = h11;
                __nv_bfloat162 pl0; pl0.x = l00; pl0.y = l01;
                __nv_bfloat162 pl1; pl1.x = l10; pl1.y = l11;
                *(__nv_bfloat162*)(outHi + (size_t)mlo * DIM + n) = ph0;
                *(__nv_bfloat162*)(outHi + (size_t)mhi * DIM + n) = ph1;
                *(__nv_bfloat162*)(outLo + (size_t)mlo * DIM + n) = pl0;
                *(__nv_bfloat162*)(outLo + (size_t)mhi * DIM + n) = pl1;
            }
        }
    } else {                          // gates: +bias, fp32 time-major
        #pragma unroll
        for (int mt = 0; mt < 2; mt++) {
            const int mlo = m0 + wm * 32 + mt * 16 + g;
            const int mhi = mlo + 8;
            const int blo = mlo >> 10, tlo = mlo & (LSEQ - 1);
            const int bhi = mhi >> 10, thi = mhi & (LSEQ - 1);
            #pragma unroll
            for (int nt = 0; nt < 8; nt++) {
                const int n = n0 + wn * 64 + nt * 8 + tg * 2;
                const float b0 = bias[n], b1 = bias[n + 1];
                float2 o0, o1;
                o0.x = acc[mt][nt][0] + b0; o0.y = acc[mt][nt][1] + b1;
                o1.x = acc[mt][nt][2] + b0; o1.y = acc[mt][nt][3] + b1;
                *(float2*)(gout + ((size_t)(tlo << 5) + blo) * GDIM + n) = o0;
                *(float2*)(gout + ((size_t)(thi << 5) + bhi) * GDIM + n) = o1;
            }
        }
    }
}

// =================== persistent bidirectional LSTM recurrence =================
__global__ void __launch_bounds__(256, 1) lstm_recur_kernel(
    const float* __restrict__ wf, const float* __restrict__ wb,
    const int* __restrict__ lengths, float* __restrict__ out)
{
    extern __shared__ float sm[];
    float* Wt = sm;               // [32][516]
    float* hs = sm + 32 * 516;    // [32][516]
    __shared__ int len_s[32];

    const int tid = threadIdx.x;
    const int dir = blockIdx.x >> 6;
    const int dc  = (blockIdx.x & 63) << 3;
    const float* w = dir ? wb : wf;

    for (int idx = tid; idx < 32 * 512; idx += 256) {
        int nl = idx & 31;
        int k  = idx >> 5;
        int c  = ((nl >> 3) << 9) + dc + (nl & 7);
        Wt[nl * 516 + k] = w[(size_t)(512 + k) * GDIM + c];
    }
    if (tid < 32) len_s[tid] = lengths[tid];
    {
        int b = tid >> 3, j = tid & 7;
        g_hstate[0][dir][b * DIM + dc + j] = 0.f;
    }
    grid_sync_();

    const int tx = tid & 31;
    const int ty = tid >> 5;
    const int jd = tx & 7;
    const int col = ((tx >> 3) << 9) + dc + jd;
    const float* gpre = g_gpre[dir];
    const float* wrow = Wt + tx * 516;
    const unsigned FULL = 0xffffffffu;

    float c0 = 0.f, c1 = 0.f, c2 = 0.f, c3 = 0.f;

    for (int s = 0; s < LSEQ; s++) {
        const int t = dir ? (LSEQ - 1 - s) : s;
        const int p = s & 1;
        const float4* hp4 = (const float4*)g_hstate[p][dir];
        float* hn = g_hstate[p ^ 1][dir];

        #pragma unroll
        for (int i = 0; i < 16; i++) {
            int idx4 = i * 256 + tid;
            int b = idx4 >> 7, kc = idx4 & 127;
            float4 v = __ldcg(hp4 + idx4);
            if (dir && t >= len_s[b] - 1) v = make_float4(0.f, 0.f, 0.f, 0.f);
            *(float4*)(hs + b * 516 + (kc << 2)) = v;
        }
        __syncthreads();

        const float* h0p = hs + (size_t)(ty     ) * 516;
        const float* h1p = hs + (size_t)(ty +  8) * 516;
        const float* h2p = hs + (size_t)(ty + 16) * 516;
        const float* h3p = hs + (size_t)(ty + 24) * 516;
        float a0 = 0.f, a1 = 0.f, a2 = 0.f, a3 = 0.f;
        #pragma unroll 4
        for (int kc = 0; kc < 128; kc++) {
            float4 wv = *(const float4*)(wrow + (kc << 2));
            float4 x0 = *(const float4*)(h0p + (kc << 2));
            float4 x1 = *(const float4*)(h1p + (kc << 2));
            float4 x2 = *(const float4*)(h2p + (kc << 2));
            float4 x3 = *(const float4*)(h3p + (kc << 2));
            a0 = fmaf(wv.x, x0.x, fmaf(wv.y, x0.y, fmaf(wv.z, x0.z, fmaf(wv.w, x0.w, a0))));
            a1 = fmaf(wv.x, x1.x, fmaf(wv.y, x1.y, fmaf(wv.z, x1.z, fmaf(wv.w, x1.w, a1))));
            a2 = fmaf(wv.x, x2.x, fmaf(wv.y, x2.y, fmaf(wv.z, x2.z, fmaf(wv.w, x2.w, a2))));
            a3 = fmaf(wv.x, x3.x, fmaf(wv.y, x3.y, fmaf(wv.z, x3.z, fmaf(wv.w, x3.w, a3))));
        }

        const float* gp = gpre + (size_t)(t << 5) * GDIM + col;
        float p0 = a0 + __ldg(gp + (size_t)(ty     ) * GDIM);
        float p1 = a1 + __ldg(gp + (size_t)(ty +  8) * GDIM);
        float p2 = a2 + __ldg(gp + (size_t)(ty + 16) * GDIM);
        float p3 = a3 + __ldg(gp + (size_t)(ty + 24) * GDIM);

        float vi0 = __shfl_sync(FULL, p0, jd),      vi1 = __shfl_sync(FULL, p1, jd);
        float vi2 = __shfl_sync(FULL, p2, jd),      vi3 = __shfl_sync(FULL, p3, jd);
        float vg0 = __shfl_sync(FULL, p0, jd + 8),  vg1 = __shfl_sync(FULL, p1, jd + 8);
        float vg2 = __shfl_sync(FULL, p2, jd + 8),  vg3 = __shfl_sync(FULL, p3, jd + 8);
        float vf0 = __shfl_sync(FULL, p0, jd + 16), vf1 = __shfl_sync(FULL, p1, jd + 16);
        float vf2 = __shfl_sync(FULL, p2, jd + 16), vf3 = __shfl_sync(FULL, p3, jd + 16);
        float vo0 = __shfl_sync(FULL, p0, jd + 24), vo1 = __shfl_sync(FULL, p1, jd + 24);
        float vo2 = __shfl_sync(FULL, p2, jd + 24), vo3 = __shfl_sync(FULL, p3, jd + 24);

        if (tx < 8) {
            const int d = dc + tx;
            {
                int b = ty;
                float cc = (dir && t >= len_s[b] - 1) ? 0.f : c0;
                cc = sigmoidf_(vf0 + 1.f) * cc + sigmoidf_(vi0) * tanhf(vg0);
                c0 = cc;
                float hh = sigmoidf_(vo0) * tanhf(cc);
                hn[b * DIM + d] = hh;
                out[(((size_t)b << 10) + t) * 1024 + (dir << 9) + d] = hh;
            }
            {
                int b = ty + 8;
                float cc = (dir && t >= len_s[b] - 1) ? 0.f : c1;
                cc = sigmoidf_(vf1 + 1.f) * cc + sigmoidf_(vi1) * tanhf(vg1);
                c1 = cc;
                float hh = sigmoidf_(vo1) * tanhf(cc);
                hn[b * DIM + d] = hh;
                out[(((size_t)b << 10) + t) * 1024 + (dir << 9) + d] = hh;
            }
            {
                int b = ty + 16;
                float cc = (dir && t >= len_s[b] - 1) ? 0.f : c2;
                cc = sigmoidf_(vf2 + 1.f) * cc + sigmoidf_(vi2) * tanhf(vg2);
                c2 = cc;
                float hh = sigmoidf_(vo2) * tanhf(cc);
                hn[b * DIM + d] = hh;
                out[(((size_t)b << 10) + t) * 1024 + (dir << 9) + d] = hh;
            }
            {
                int b = ty + 24;
                float cc = (dir && t >= len_s[b] - 1) ? 0.f : c3;
                cc = sigmoidf_(vf3 + 1.f) * cc + sigmoidf_(vi3) * tanhf(vg3);
                c3 = cc;
                float hh = sigmoidf_(vo3) * tanhf(cc);
                hn[b * DIM + d] = hh;
                out[(((size_t)b << 10) + t) * 1024 + (dir << 9) + d] = hh;
            }
        }
        grid_sync_();
    }
}

// =================== launch ===================================================
extern "C" void kernel_launch(void* const* d_in, const int* in_sizes, int n_in,
                              void* d_out, int out_size)
{
    (void)in_sizes; (void)n_in; (void)out_size;
    const int*   x        = (const int*)  d_in[0];
    const int*   lengths  = (const int*)  d_in[1];
    const float* embed_w  = (const float*)d_in[2];
    const float* c1w = (const float*)d_in[3];
    const float* c1b = (const float*)d_in[4];
    const float* c2w = (const float*)d_in[5];
    const float* c2b = (const float*)d_in[6];
    const float* c3w = (const float*)d_in[7];
    const float* c3b = (const float*)d_in[8];
    const float* wf  = (const float*)d_in[9];
    const float* bf  = (const float*)d_in[10];
    const float* wb  = (const float*)d_in[11];
    const float* bb  = (const float*)d_in[12];
    const float* s1 = (const float*)d_in[13]; const float* o1 = (const float*)d_in[14];
    const float* m1 = (const float*)d_in[15]; const float* v1 = (const float*)d_in[16];
    const float* s2 = (const float*)d_in[17]; const float* o2 = (const float*)d_in[18];
    const float* m2 = (const float*)d_in[19]; const float* v2 = (const float*)d_in[20];
    const float* s3 = (const float*)d_in[21]; const float* o3 = (const float*)d_in[22];
    const float* m3 = (const float*)d_in[23]; const float* v3 = (const float*)d_in[24];
    float* out = (float*)d_out;

    __nv_bfloat16 *aHi, *aLo, *bHi, *bLo, *wC, *wG;
    cudaGetSymbolAddress((void**)&aHi, g_aHi);
    cudaGetSymbolAddress((void**)&aLo, g_aLo);
    cudaGetSymbolAddress((void**)&bHi, g_bHi);
    cudaGetSymbolAddress((void**)&bLo, g_bLo);
    cudaGetSymbolAddress((void**)&wC, g_wConv);
    cudaGetSymbolAddress((void**)&wG, g_wGate);
    float* gpre;
    cudaGetSymbolAddress((void**)&gpre, g_gpre);

    const int SMEM_GEMM  = 65536;
    const int SMEM_RECUR = 2 * 32 * 516 * sizeof(float);
    cudaFuncSetAttribute(mma_gemm_kernel,
                         cudaFuncAttributeMaxDynamicSharedMemorySize, SMEM_GEMM);
    cudaFuncSetAttribute(lstm_recur_kernel,
                         cudaFuncAttributeMaxDynamicSharedMemorySize, SMEM_RECUR);

    bnprep_kernel<<<1, 512>>>(c1b, s1, o1, m1, v1,
                              c2b, s2, o2, m2, v2,
                              c3b, s3, o3, m3, v3);

    const int NWC = (DIM * 4608 + 255) / 256;
    wprep_conv_kernel<<<NWC, 256>>>(c1w, 0);
    wprep_conv_kernel<<<NWC, 256>>>(c2w, 1);
    wprep_conv_kernel<<<NWC, 256>>>(c3w, 2);
    const int NWG = (GDIM * 1536 + 255) / 256;
    wprep_gate_kernel<<<NWG, 256>>>(wf, 0);
    wprep_gate_kernel<<<NWG, 256>>>(wb, 1);

    embed_kernel<<<MTOT, 128>>>(x, embed_w);

    dim3 gconv(MTOT / 128, DIM / 128);       // (256, 4)
    mma_gemm_kernel<<<gconv, 256, SMEM_GEMM>>>(aHi, aLo, wC + 0 * (size_t)DIM * 4608,
        4608, 1, 0, bHi, bLo, nullptr, nullptr);
    mma_gemm_kernel<<<gconv, 256, SMEM_GEMM>>>(bHi, bLo, wC + 1 * (size_t)DIM * 4608,
        4608, 1, 1, aHi, aLo, nullptr, nullptr);
    mma_gemm_kernel<<<gconv, 256, SMEM_GEMM>>>(aHi, aLo, wC + 2 * (size_t)DIM * 4608,
        4608, 1, 2, bHi, bLo, nullptr, nullptr);

    dim3 ggate(MTOT / 128, GDIM / 128);      // (256, 16)
    mma_gemm_kernel<<<ggate, 256, SMEM_GEMM>>>(bHi, bLo, wG + 0 * (size_t)GDIM * 1536,
        1536, 0, -1, nullptr, nullptr, bf, gpre + 0);
    mma_gemm_kernel<<<ggate, 256, SMEM_GEMM>>>(bHi, bLo, wG + 1 * (size_t)GDIM * 1536,
        1536, 0, -1, nullptr, nullptr, bb, gpre + (size_t)MTOT * GDIM);

    lstm_recur_kernel<<<GRID_BLOCKS, 256, SMEM_RECUR>>>(wf, wb, lengths, out);
}